// round 12
// baseline (speedup 1.0000x reference)
#include <cuda_runtime.h>
#include <cstdint>
#include <cstddef>

// ---------------- problem constants ----------------
#define DRUGN 100000
#define DISN  100000
#define NRD   200000            // DRUGN + DISN
#define HIDD  64
#define ERR_  1600000
#define EDD_  1600000
#define ERD_  3200000
#define ETOT  (ERR_ + EDD_ + ERD_)
#define NROWS (DRUGN + DISN + NRD)    // 400000 unified rows: rr | dd | rd
#define NBLK  ((NROWS + 1023) / 1024) // 391 scan blocks
#define DEGN  (2*DRUGN + 2*DISN + 2*NRD)  // 800000 degree slots (int counts; val==1)
#define EPSV  0.1f

// ---------------- output layout (floats) ----------------
#define OFF_E      0            // drugE || disE  (contiguous 12.8M)
#define OFF_ALL    12800000     // drugAll || disAll
#define OFF_RDEMB  25600000     // rd_drug || rd_dis  (= raw embeddings)
#define OFF_LOSS   38400000
#define OFF_STACK  38400001ull  // rd_stack (200000, 4, 64)

// ---------------- scratch (device globals; zero at load, re-zeroed by cleanup) ------
__device__ int   g_deg  [DEGN];          // degree counts (val == 1)
__device__ int   g_lbstate[NBLK];        // lookback: (status<<28)|sum, status 1=agg 2=incl
__device__ int   g_lptr [NROWS + 1];     // ABSOLUTE exclusive prefixes
__device__ int   g_cursor[NROWS];        // fill cursors (absolute)
__device__ int2  g_epair[ETOT];          // (col, float-bits of vn), unified CSR order
__device__ float g_cur0 [NRD*HIDD];      // gated embeddings rr0 || dd0
__device__ float g_curA [NRD*HIDD];      // ping-pong state buffers
__device__ float g_curB [NRD*HIDD];
__device__ float g_sum  [NRD*HIDD];      // running sum for the layer mean

// ---------------- JAX-exact threefry2x32 (20 rounds) ----------------
__host__ __device__ __forceinline__ void threefry2x32(
    uint32_t k0, uint32_t k1, uint32_t x0, uint32_t x1,
    uint32_t& o0, uint32_t& o1)
{
    uint32_t ks2 = k0 ^ k1 ^ 0x1BD11BDAu;
#define TFR(r) { x0 += x1; x1 = (x1 << (r)) | (x1 >> (32 - (r))); x1 ^= x0; }
    x0 += k0; x1 += k1;
    TFR(13) TFR(15) TFR(26) TFR(6)
    x0 += k1;  x1 += ks2 + 1u;
    TFR(17) TFR(29) TFR(16) TFR(24)
    x0 += ks2; x1 += k0 + 2u;
    TFR(13) TFR(15) TFR(26) TFR(6)
    x0 += k0;  x1 += k1 + 3u;
    TFR(17) TFR(29) TFR(16) TFR(24)
    x0 += k1;  x1 += ks2 + 4u;
    TFR(13) TFR(15) TFR(26) TFR(6)
    x0 += ks2; x1 += k0 + 5u;
#undef TFR
    o0 = x0; o1 = x1;
}

__device__ __forceinline__ float u01(uint32_t b) {
    return __uint_as_float((b >> 9) | 0x3F800000u) - 1.0f;
}
__device__ __forceinline__ float sgnf(float x) {
    return (x > 0.0f) ? 1.0f : ((x < 0.0f) ? -1.0f : 0.0f);
}

// ---------------- fused gate + init (one pass over both embeddings) ----------------
__global__ void gateinit_kernel(const float* __restrict__ de, const float* __restrict__ se,
                                const float* __restrict__ Wr, const float* __restrict__ br,
                                const float* __restrict__ Wd, const float* __restrict__ bd,
                                float* __restrict__ out)
{
    __shared__ float sW[HIDD * HIDD];
    __shared__ float sb[HIDD];
    __shared__ float sE[4][HIDD];
    int t = threadIdx.x;                    // 256 threads
    int half = (blockIdx.x >= 1024);
    const float* emb = half ? se : de;
    const float* W   = half ? Wd : Wr;
    const float* b   = half ? bd : br;
    int nodeBase = half ? DRUGN : 0;
    for (int i = t; i < HIDD * HIDD; i += 256) sW[i] = W[i];
    if (t < HIDD) sb[t] = b[t];
    int j  = t & 63;
    int rs = t >> 6;
    int bl = blockIdx.x & 1023;
    for (int base = bl * 4; base < DRUGN; base += 1024 * 4) {
        int rown = base + rs;
        __syncthreads();
        float ev = emb[rown * HIDD + j];
        sE[rs][j] = ev;
        __syncthreads();
        float acc = sb[j];
#pragma unroll
        for (int k = 0; k < HIDD; k++) acc = fmaf(sE[rs][k], sW[k * HIDD + j], acc);
        float gt = 1.0f / (1.0f + expf(-acc));
        float gv = ev * gt;
        size_t uidx = (size_t)(nodeBase + rown) * HIDD + j;
        g_cur0[uidx] = gv;                  // layer-0 prop input (rr0 || dd0)
        g_sum [uidx] = gv;                  // all_*[0] entry (unnormalized)
        out[OFF_RDEMB + uidx] = ev;         // rd_drug || rd_dis (= raw embeddings)
        out[OFF_STACK + (size_t)(nodeBase + rown) * 256 + j] = ev;  // stack layer 0
    }
    if (blockIdx.x == 0 && t == 0) out[OFF_LOSS] = 0.0f;
}

// ---------------- degree counts over ALL 3 edge lists (val == 1) ----------------
__global__ void degcnt_all(const int* __restrict__ rr_r, const int* __restrict__ rr_c,
                           const int* __restrict__ dd_r, const int* __restrict__ dd_c,
                           const int* __restrict__ rd_r, const int* __restrict__ rd_c)
{
    int e = blockIdx.x * blockDim.x + threadIdx.x;
    if (e >= ETOT) return;
    int r, c; int *dr, *dc;
    if (e < ERR_) {
        r = rr_r[e]; c = rr_c[e];
        dr = g_deg;              dc = g_deg + DRUGN;
    } else if (e < ERR_ + EDD_) {
        int k = e - ERR_;
        r = dd_r[k]; c = dd_c[k];
        dr = g_deg + 2*DRUGN;    dc = g_deg + 2*DRUGN + DISN;
    } else {
        int k = e - ERR_ - EDD_;
        r = rd_r[k]; c = rd_c[k];
        dr = g_deg + 2*DRUGN + 2*DISN; dc = dr + NRD;
    }
    atomicAdd(dr + r, 1);
    atomicAdd(dc + c, 1);
}

// row count for unified row i lives in the corresponding dr slot
__device__ __forceinline__ int row_count(int i)
{
    if (i < DRUGN)       return g_deg[i];                         // dr_rr
    if (i < 2*DRUGN)     return g_deg[2*DRUGN + (i - DRUGN)];     // dr_dd
    return g_deg[2*DRUGN + 2*DISN + (i - NRD)];                   // dr_rd
}

// ---------------- single-pass decoupled-lookback scan ----------------
// Packed word protocol: (status<<28)|sum ; sum < 6.4M < 2^28. No fence needed —
// all communicated data lives in the single published word.
__global__ void scan_lb_kernel()
{
    __shared__ int sw[32];
    __shared__ int s_excl;
    int b = blockIdx.x, t = threadIdx.x;
    int lane = t & 31, wid = t >> 5;
    int i = b * 1024 + t;
    int v = (i < NROWS) ? row_count(i) : 0;
    int inc = v;
#pragma unroll
    for (int o = 1; o < 32; o <<= 1) {
        int u = __shfl_up_sync(0xffffffffu, inc, o);
        if (lane >= o) inc += u;
    }
    if (lane == 31) sw[wid] = inc;
    __syncthreads();
    if (wid == 0) {
        int s = sw[lane];
#pragma unroll
        for (int o = 1; o < 32; o <<= 1) {
            int u = __shfl_up_sync(0xffffffffu, s, o);
            if (lane >= o) s += u;
        }
        sw[lane] = s;
    }
    __syncthreads();
    if (t == 0) {
        int tot = sw[31];
        if (b == 0) {
            s_excl = 0;
            atomicExch(g_lbstate + 0, (2 << 28) | tot);     // inclusive
        } else {
            atomicExch(g_lbstate + b, (1 << 28) | tot);     // aggregate
            int run = 0, j = b - 1;
            while (true) {
                int s = *(volatile int*)(g_lbstate + j);
                int st = s >> 28;
                if (st == 0) continue;                       // spin
                run += s & 0x0FFFFFFF;
                if (st == 2) break;
                j--;
            }
            s_excl = run;
            atomicExch(g_lbstate + b, (2 << 28) | (run + tot));
        }
    }
    __syncthreads();
    int base = s_excl;
    int excl = base + (wid ? sw[wid - 1] : 0) + inc - v;    // absolute exclusive
    if (i <= NROWS) g_lptr[i] = excl;                       // includes sentinel
    if (i <  NROWS) g_cursor[i] = excl;
}

// ---------------- fill: vn inline (val==1), absolute cursor ----------------
__global__ void fill_all(const int* __restrict__ rr_r, const int* __restrict__ rr_c,
                         const int* __restrict__ dd_r, const int* __restrict__ dd_c,
                         const int* __restrict__ rd_r, const int* __restrict__ rd_c)
{
    int e = blockIdx.x * blockDim.x + threadIdx.x;
    if (e >= ETOT) return;
    int r, c; const int *dr, *dc; int rowOff, colOff;
    if (e < ERR_) {
        r = rr_r[e]; c = rr_c[e];
        dr = g_deg;                    dc = g_deg + DRUGN;
        rowOff = 0;                    colOff = 0;
    } else if (e < ERR_ + EDD_) {
        int k = e - ERR_;
        r = dd_r[k]; c = dd_c[k];
        dr = g_deg + 2*DRUGN;          dc = g_deg + 2*DRUGN + DISN;
        rowOff = DRUGN;                colOff = DRUGN;
    } else {
        int k = e - ERR_ - EDD_;
        r = rd_r[k]; c = rd_c[k];
        dr = g_deg + 2*DRUGN + 2*DISN; dc = dr + NRD;
        rowOff = NRD;                  colOff = 0;
    }
    float vn = rsqrtf(fmaxf((float)dr[r] * (float)dc[c], 1e-12f));
    int p = atomicAdd(g_cursor + (r + rowOff), 1);
    g_epair[p] = make_int2(c + colOff, __float_as_int(vn));
}

// ---------------- fused iteration: dual-row edge streaming ----------------
// Warp handles node gw: A-row gw (rr/dd prop) and B-row gw+NRD (rd prop), with the
// two edge lists streamed as ONE concatenated sequence in full 32-lane batches.
// EMB=1: B-row gathers index concat(drug_emb, dis_emb) directly (iteration 0).
template<int EMB>
__global__ void iter_kernel(const float2* __restrict__ xA, const float2* __restrict__ xB,
                            float2* __restrict__ xOut,
                            const float2* __restrict__ demb, const float2* __restrict__ semb,
                            unsigned fk0, unsigned fk1, int iter, float* __restrict__ out)
{
    int gw   = (blockIdx.x * blockDim.x + threadIdx.x) >> 5;   // node 0..NRD-1
    int lane = threadIdx.x & 31;
    if (gw >= NRD) return;

    int pa0 = g_lptr[gw],       lenA = g_lptr[gw + 1] - pa0;
    int pb0 = g_lptr[gw + NRD], lenB = g_lptr[gw + NRD + 1] - pb0;
    int total = lenA + lenB;

    float dx = 0.0f, dy = 0.0f, rx = 0.0f, ry = 0.0f;
    for (int base = 0; base < total; base += 32) {
        int k = base + lane;
        int2 ee = make_int2(0, 0);
        if (k < lenA)       ee = __ldg(g_epair + pa0 + k);
        else if (k < total) ee = __ldg(g_epair + pb0 + (k - lenA));
        int m = min(32, total - base);
#pragma unroll 4
        for (int jj = 0; jj < m; jj++) {
            int   c = __shfl_sync(0xffffffffu, ee.x, jj);
            float v = __int_as_float(__shfl_sync(0xffffffffu, ee.y, jj));
            if (base + jj < lenA) {                         // uniform branch
                float2 xv = __ldg(xA + (size_t)c * 32 + lane);
                dx = fmaf(v, xv.x, dx);
                dy = fmaf(v, xv.y, dy);
            } else {
                float2 xv;
                if (EMB) {
                    const float2* xb = (c < DRUGN) ? (demb + (size_t)c * 32)
                                                   : (semb + (size_t)(c - DRUGN) * 32);
                    xv = __ldg(xb + lane);
                } else {
                    xv = __ldg(xB + (size_t)c * 32 + lane);
                }
                rx = fmaf(v, xv.x, rx);
                ry = fmaf(v, xv.y, ry);
            }
        }
    }

    // partitionable threefry noise: bits[m] = o0^o1 of threefry(key, 0, m)
    unsigned m0 = (unsigned)gw * 64u + (unsigned)(lane * 2);
    uint32_t a0, b0, a1, b1;
    threefry2x32(fk0, fk1, 0u, m0,      a0, b0);
    threefry2x32(fk0, fk1, 0u, m0 + 1u, a1, b1);
    float u0 = u01(a0 ^ b0);
    float u1 = u01(a1 ^ b1);

    float nn = u0 * u0 + u1 * u1;
#pragma unroll
    for (int o = 16; o; o >>= 1) nn += __shfl_xor_sync(0xffffffffu, nn, o);
    float sc = EPSV / fmaxf(sqrtf(nn), 1e-12f);

    rx += sgnf(rx) * u0 * sc;
    ry += sgnf(ry) * u1 * sc;

    float nr = rx * rx + ry * ry;
    float np = dx * dx + dy * dy;
#pragma unroll
    for (int o = 16; o; o >>= 1) {
        nr += __shfl_xor_sync(0xffffffffu, nr, o);
        np += __shfl_xor_sync(0xffffffffu, np, o);
    }
    float ir = 1.0f / fmaxf(sqrtf(nr), 1e-12f);
    float ip = 1.0f / fmaxf(sqrtf(np), 1e-12f);

    // rd_stack[:, iter+1, :] = l2n(noised r0)
    size_t so = OFF_STACK + (size_t)gw * 256 + (size_t)(iter + 1) * 64 + lane * 2;
    out[so]     = rx * ir;
    out[so + 1] = ry * ir;

    float2* sum2 = reinterpret_cast<float2*>(g_sum) + (size_t)gw * 32 + lane;
    float2 s = *sum2;

    if (iter < 2) {
        s.x += dx * ip;
        s.y += dy * ip;
        *sum2 = s;
        xOut[(size_t)gw * 32 + lane] = make_float2(0.5f * (dx + rx), 0.5f * (dy + ry));
    } else {
        // fused final: v = mean of 4 layer terms; All = 0.5*rawEmb + 0.5*v
        float vx = (s.x + dx * ip) * 0.25f;
        float vy = (s.y + dy * ip) * 0.25f;
        float2 e = (gw < DRUGN) ? __ldg(demb + (size_t)gw * 32 + lane)
                                : __ldg(semb + (size_t)(gw - DRUGN) * 32 + lane);
        size_t uidx = (size_t)gw * 64 + lane * 2;
        out[OFF_E   + uidx]     = vx;
        out[OFF_E   + uidx + 1] = vy;
        out[OFF_ALL + uidx]     = 0.5f * e.x + 0.5f * vx;
        out[OFF_ALL + uidx + 1] = 0.5f * e.y + 0.5f * vy;
    }
}

// ---------------- cleanup: restore zero-state for next call (graph-legal) ----------
__global__ void cleanup_kernel()
{
    int i = blockIdx.x * blockDim.x + threadIdx.x;
    if (i < DEGN) g_deg[i] = 0;
    if (i < NBLK) g_lbstate[i] = 0;
}

// ---------------- host orchestration (graph-capturable) ----------------
extern "C" void kernel_launch(void* const* d_in, const int* in_sizes, int n_in,
                              void* d_out, int out_size)
{
    const float* drug_emb = (const float*)d_in[0];
    const float* dis_emb  = (const float*)d_in[1];
    const float* Wr = (const float*)d_in[2];
    const float* br = (const float*)d_in[3];
    const float* Wd = (const float*)d_in[4];
    const float* bd = (const float*)d_in[5];
    const int*   rr_row = (const int*)d_in[6];
    const int*   rr_col = (const int*)d_in[7];
    const int*   dd_row = (const int*)d_in[9];
    const int*   dd_col = (const int*)d_in[10];
    const int*   rd_row = (const int*)d_in[12];
    const int*   rd_col = (const int*)d_in[13];
    float* out = (float*)d_out;

    float *cur0, *curA, *curB;
    cudaGetSymbolAddress((void**)&cur0, g_cur0);
    cudaGetSymbolAddress((void**)&curA, g_curA);
    cudaGetSymbolAddress((void**)&curB, g_curB);

    // launch 1: fused gate + init
    gateinit_kernel<<<2048, 256>>>(drug_emb, dis_emb, Wr, br, Wd, bd, out);
    // launch 2: degree counts (g_deg zero from load / previous cleanup)
    degcnt_all<<<(ETOT + 255) / 256, 256>>>(rr_row, rr_col, dd_row, dd_col, rd_row, rd_col);
    // launch 3: single-pass lookback scan (absolute lptr + cursor + sentinel)
    scan_lb_kernel<<<NBLK, 1024>>>();
    // launch 4: fill with inline vn
    fill_all<<<(ETOT + 255) / 256, 256>>>(rr_row, rr_col, dd_row, dd_col, rd_row, rd_col);

    // fold_in keys: threefry(key=[0,1], count=[0,i])
    unsigned fk0[3], fk1[3];
    for (int i = 0; i < 3; i++)
        threefry2x32(0u, 1u, 0u, (unsigned)i, fk0[i], fk1[i]);

    // launch 5 (captured by ncu): iteration 0 — rd gathers read embeddings directly
    iter_kernel<1><<<NRD * 32 / 256, 256>>>((const float2*)cur0, nullptr,
                                            (float2*)curA,
                                            (const float2*)drug_emb, (const float2*)dis_emb,
                                            fk0[0], fk1[0], 0, out);
    // launch 6: iteration 1
    iter_kernel<0><<<NRD * 32 / 256, 256>>>((const float2*)curA, (const float2*)curA,
                                            (float2*)curB,
                                            (const float2*)drug_emb, (const float2*)dis_emb,
                                            fk0[1], fk1[1], 1, out);
    // launch 7: iteration 2 (final fused)
    iter_kernel<0><<<NRD * 32 / 256, 256>>>((const float2*)curB, (const float2*)curB,
                                            (float2*)curA,
                                            (const float2*)drug_emb, (const float2*)dis_emb,
                                            fk0[2], fk1[2], 2, out);
    // launch 8: restore zero-state for the next (deterministic) call
    cleanup_kernel<<<(DEGN + 255) / 256, 256>>>();
}

// round 13
// speedup vs baseline: 1.5853x; 1.5853x over previous
#include <cuda_runtime.h>
#include <cstdint>
#include <cstddef>

// ---------------- problem constants ----------------
#define DRUGN 100000
#define DISN  100000
#define NRD   200000            // DRUGN + DISN
#define HIDD  64
#define ERR_  1600000
#define EDD_  1600000
#define ERD_  3200000
#define ETOT  (ERR_ + EDD_ + ERD_)
#define NROWS (DRUGN + DISN + NRD)    // 400000 unified rows: rr | dd | rd
#define NBLK  ((NROWS + 1023) / 1024) // 391 scan blocks
#define DEGN  (2*DRUGN + 2*DISN + 2*NRD)  // 800000 degree slots (int counts; val==1)
#define EPSV  0.1f

// ---------------- output layout (floats) ----------------
#define OFF_E      0            // drugE || disE  (contiguous 12.8M)
#define OFF_ALL    12800000     // drugAll || disAll
#define OFF_RDEMB  25600000     // rd_drug || rd_dis  (= raw embeddings)
#define OFF_LOSS   38400000
#define OFF_STACK  38400001ull  // rd_stack (200000, 4, 64)

// ---------------- scratch (device globals) ----------------
__device__ int   g_deg  [DEGN];          // degree counts (val == 1)
__device__ int   g_lptr [NROWS + 1];     // block-local exclusive prefixes
__device__ int   g_cursor[NROWS];        // fill cursors (block-local)
__device__ int   g_bsum [NBLK];          // exclusive block offsets
__device__ int2  g_epair[ETOT];          // (col, float-bits of vn), unified CSR order
__device__ float g_cur0 [NRD*HIDD];      // gated embeddings rr0 || dd0
__device__ float g_curA [NRD*HIDD];      // ping-pong state buffers
__device__ float g_curB [NRD*HIDD];
__device__ float g_sum  [NRD*HIDD];      // running sum for the layer mean

// ---------------- JAX-exact threefry2x32 (20 rounds) ----------------
__host__ __device__ __forceinline__ void threefry2x32(
    uint32_t k0, uint32_t k1, uint32_t x0, uint32_t x1,
    uint32_t& o0, uint32_t& o1)
{
    uint32_t ks2 = k0 ^ k1 ^ 0x1BD11BDAu;
#define TFR(r) { x0 += x1; x1 = (x1 << (r)) | (x1 >> (32 - (r))); x1 ^= x0; }
    x0 += k0; x1 += k1;
    TFR(13) TFR(15) TFR(26) TFR(6)
    x0 += k1;  x1 += ks2 + 1u;
    TFR(17) TFR(29) TFR(16) TFR(24)
    x0 += ks2; x1 += k0 + 2u;
    TFR(13) TFR(15) TFR(26) TFR(6)
    x0 += k0;  x1 += k1 + 3u;
    TFR(17) TFR(29) TFR(16) TFR(24)
    x0 += k1;  x1 += ks2 + 4u;
    TFR(13) TFR(15) TFR(26) TFR(6)
    x0 += ks2; x1 += k0 + 5u;
#undef TFR
    o0 = x0; o1 = x1;
}

__device__ __forceinline__ float u01(uint32_t b) {
    return __uint_as_float((b >> 9) | 0x3F800000u) - 1.0f;
}
__device__ __forceinline__ float sgnf(float x) {
    return (x > 0.0f) ? 1.0f : ((x < 0.0f) ? -1.0f : 0.0f);
}

// ---------------- fused gate + init (one pass over both embeddings) ----------------
__global__ void gateinit_kernel(const float* __restrict__ de, const float* __restrict__ se,
                                const float* __restrict__ Wr, const float* __restrict__ br,
                                const float* __restrict__ Wd, const float* __restrict__ bd,
                                float* __restrict__ out)
{
    __shared__ float sW[HIDD * HIDD];
    __shared__ float sb[HIDD];
    __shared__ float sE[4][HIDD];
    int t = threadIdx.x;                    // 256 threads
    int half = (blockIdx.x >= 1024);
    const float* emb = half ? se : de;
    const float* W   = half ? Wd : Wr;
    const float* b   = half ? bd : br;
    int nodeBase = half ? DRUGN : 0;
    for (int i = t; i < HIDD * HIDD; i += 256) sW[i] = W[i];
    if (t < HIDD) sb[t] = b[t];
    int j  = t & 63;
    int rs = t >> 6;
    int bl = blockIdx.x & 1023;
    for (int base = bl * 4; base < DRUGN; base += 1024 * 4) {
        int rown = base + rs;
        __syncthreads();
        float ev = emb[rown * HIDD + j];
        sE[rs][j] = ev;
        __syncthreads();
        float acc = sb[j];
#pragma unroll
        for (int k = 0; k < HIDD; k++) acc = fmaf(sE[rs][k], sW[k * HIDD + j], acc);
        float gt = 1.0f / (1.0f + expf(-acc));
        float gv = ev * gt;
        size_t uidx = (size_t)(nodeBase + rown) * HIDD + j;
        g_cur0[uidx] = gv;                  // layer-0 prop input (rr0 || dd0)
        g_sum [uidx] = gv;                  // all_*[0] entry (unnormalized)
        out[OFF_RDEMB + uidx] = ev;         // rd_drug || rd_dis (= raw embeddings)
        out[OFF_STACK + (size_t)(nodeBase + rown) * 256 + j] = ev;  // stack layer 0
    }
    if (blockIdx.x == 0 && t == 0) out[OFF_LOSS] = 0.0f;
}

// ---------------- degree counts over ALL 3 edge lists (val == 1) ----------------
__global__ void degcnt_all(const int* __restrict__ rr_r, const int* __restrict__ rr_c,
                           const int* __restrict__ dd_r, const int* __restrict__ dd_c,
                           const int* __restrict__ rd_r, const int* __restrict__ rd_c)
{
    int e = blockIdx.x * blockDim.x + threadIdx.x;
    if (e >= ETOT) return;
    int r, c; int *dr, *dc;
    if (e < ERR_) {
        r = rr_r[e]; c = rr_c[e];
        dr = g_deg;              dc = g_deg + DRUGN;
    } else if (e < ERR_ + EDD_) {
        int k = e - ERR_;
        r = dd_r[k]; c = dd_c[k];
        dr = g_deg + 2*DRUGN;    dc = g_deg + 2*DRUGN + DISN;
    } else {
        int k = e - ERR_ - EDD_;
        r = rd_r[k]; c = rd_c[k];
        dr = g_deg + 2*DRUGN + 2*DISN; dc = dr + NRD;
    }
    atomicAdd(dr + r, 1);
    atomicAdd(dc + c, 1);
}

// row count for unified row i lives in the corresponding dr slot
__device__ __forceinline__ int row_count(int i)
{
    if (i < DRUGN)       return g_deg[i];                         // dr_rr
    if (i < 2*DRUGN)     return g_deg[2*DRUGN + (i - DRUGN)];     // dr_dd
    return g_deg[2*DRUGN + 2*DISN + (i - NRD)];                   // dr_rd
}

// ---------------- scan1: block-local exclusive prefix + cursor + block totals -------
__global__ void scan1_kernel()
{
    __shared__ int sw[32];
    int b = blockIdx.x, t = threadIdx.x;
    int lane = t & 31, wid = t >> 5;
    int i = b * 1024 + t;
    int v = (i < NROWS) ? row_count(i) : 0;
    int inc = v;
#pragma unroll
    for (int o = 1; o < 32; o <<= 1) {
        int u = __shfl_up_sync(0xffffffffu, inc, o);
        if (lane >= o) inc += u;
    }
    if (lane == 31) sw[wid] = inc;
    __syncthreads();
    if (wid == 0) {
        int s = sw[lane];
#pragma unroll
        for (int o = 1; o < 32; o <<= 1) {
            int u = __shfl_up_sync(0xffffffffu, s, o);
            if (lane >= o) s += u;
        }
        sw[lane] = s;
    }
    __syncthreads();
    int woff = wid ? sw[wid - 1] : 0;
    int excl = woff + inc - v;
    if (i <= NROWS) g_lptr[i] = excl;       // includes sentinel slot i == NROWS
    if (i <  NROWS) g_cursor[i] = excl;
    if (t == 0)     g_bsum[b] = sw[31];
}

// ---------------- scan2: exclusive scan of 391 block totals (1 block) ----------------
__global__ void scan2_kernel()
{
    __shared__ int sw[16];
    int t = threadIdx.x;           // 512 threads
    int lane = t & 31, wid = t >> 5;
    int v = (t < NBLK) ? g_bsum[t] : 0;
    int inc = v;
#pragma unroll
    for (int o = 1; o < 32; o <<= 1) {
        int u = __shfl_up_sync(0xffffffffu, inc, o);
        if (lane >= o) inc += u;
    }
    if (lane == 31) sw[wid] = inc;
    __syncthreads();
    if (wid == 0 && lane < 16) {
        int s = sw[lane];
#pragma unroll
        for (int o = 1; o < 16; o <<= 1) {
            int u = __shfl_up_sync(0x0000ffffu, s, o);
            if (lane >= o) s += u;
        }
        sw[lane] = s;
    }
    __syncthreads();
    int excl = (wid ? sw[wid - 1] : 0) + inc - v;
    if (t < NBLK) g_bsum[t] = excl;
}

// ---------------- fill: vn inline (val==1), absolute pos = cursor + bsum ------------
__global__ void fill_all(const int* __restrict__ rr_r, const int* __restrict__ rr_c,
                         const int* __restrict__ dd_r, const int* __restrict__ dd_c,
                         const int* __restrict__ rd_r, const int* __restrict__ rd_c)
{
    int e = blockIdx.x * blockDim.x + threadIdx.x;
    if (e >= ETOT) return;
    int r, c; const int *dr, *dc; int rowOff, colOff;
    if (e < ERR_) {
        r = rr_r[e]; c = rr_c[e];
        dr = g_deg;                    dc = g_deg + DRUGN;
        rowOff = 0;                    colOff = 0;
    } else if (e < ERR_ + EDD_) {
        int k = e - ERR_;
        r = dd_r[k]; c = dd_c[k];
        dr = g_deg + 2*DRUGN;          dc = g_deg + 2*DRUGN + DISN;
        rowOff = DRUGN;                colOff = DRUGN;
    } else {
        int k = e - ERR_ - EDD_;
        r = rd_r[k]; c = rd_c[k];
        dr = g_deg + 2*DRUGN + 2*DISN; dc = dr + NRD;
        rowOff = NRD;                  colOff = 0;
    }
    float vn = rsqrtf(fmaxf((float)dr[r] * (float)dc[c], 1e-12f));
    int urow = r + rowOff;
    int p = atomicAdd(g_cursor + urow, 1) + g_bsum[urow >> 10];
    g_epair[p] = make_int2(c + colOff, __float_as_int(vn));
}

// ---------------- half-warp float4 row gather ----------------
// Warp = 2 halves of 16 lanes; each half processes a different edge of the same row.
// Lane covers features [el*4, el*4+4) via one LDG.128. Accumulators are duplicated
// across halves and merged by the caller with shfl_xor(16).
__device__ __forceinline__ void row_gather4(int p0, int p1, const float4* __restrict__ x,
                                            int lane, int eh, int el, float4& a)
{
    for (int base = p0; base < p1; base += 32) {
        int idx = base + lane;
        int2 ee = (idx < p1) ? __ldg(g_epair + idx) : make_int2(0, 0);
        int m = min(32, p1 - base);
        int half = (m + 1) >> 1;
#pragma unroll 4
        for (int jj = 0; jj < half; jj++) {
            int j = 2 * jj + eh;                               // convergent: all lanes loop same count
            int   c = __shfl_sync(0xffffffffu, ee.x, j);
            float v = __int_as_float(__shfl_sync(0xffffffffu, ee.y, j));
            if (j < m) {
                float4 xv = __ldg(x + (size_t)c * 16 + el);
                a.x = fmaf(v, xv.x, a.x);
                a.y = fmaf(v, xv.y, a.y);
                a.z = fmaf(v, xv.z, a.z);
                a.w = fmaf(v, xv.w, a.w);
            }
        }
    }
}

// iter-0 rd gather: columns index concat(drug_emb, dis_emb) — per-col pointer select
__device__ __forceinline__ void row_gather4_emb(int p0, int p1,
                                                const float4* __restrict__ de,
                                                const float4* __restrict__ se,
                                                int lane, int eh, int el, float4& a)
{
    for (int base = p0; base < p1; base += 32) {
        int idx = base + lane;
        int2 ee = (idx < p1) ? __ldg(g_epair + idx) : make_int2(0, 0);
        int m = min(32, p1 - base);
        int half = (m + 1) >> 1;
#pragma unroll 4
        for (int jj = 0; jj < half; jj++) {
            int j = 2 * jj + eh;
            int   c = __shfl_sync(0xffffffffu, ee.x, j);
            float v = __int_as_float(__shfl_sync(0xffffffffu, ee.y, j));
            if (j < m) {
                const float4* xb = (c < DRUGN) ? (de + (size_t)c * 16)
                                               : (se + (size_t)(c - DRUGN) * 16);
                float4 xv = __ldg(xb + el);
                a.x = fmaf(v, xv.x, a.x);
                a.y = fmaf(v, xv.y, a.y);
                a.z = fmaf(v, xv.z, a.z);
                a.w = fmaf(v, xv.w, a.w);
            }
        }
    }
}

// ---------------- fused iteration: spmm both rows + noise + norms + update ----------
// iter==2 additionally emits drugE/disE/drugAll/disAll (final_kernel fused in).
template<int EMB>
__global__ void iter_kernel(const float4* __restrict__ xA, const float4* __restrict__ xB,
                            float4* __restrict__ xOut,
                            const float4* __restrict__ demb, const float4* __restrict__ semb,
                            unsigned fk0, unsigned fk1, int iter, float* __restrict__ out)
{
    int gw   = (blockIdx.x * blockDim.x + threadIdx.x) >> 5;   // node 0..NRD-1
    int lane = threadIdx.x & 31;
    if (gw >= NRD) return;
    int eh = lane >> 4, el = lane & 15;

    int pa0 = g_lptr[gw]           + g_bsum[gw >> 10];
    int pa1 = g_lptr[gw + 1]       + g_bsum[(gw + 1) >> 10];
    int pb0 = g_lptr[gw + NRD]     + g_bsum[(gw + NRD) >> 10];
    int pb1 = g_lptr[gw + NRD + 1] + g_bsum[(gw + NRD + 1) >> 10];

    float4 d = make_float4(0.f, 0.f, 0.f, 0.f);
    float4 r = make_float4(0.f, 0.f, 0.f, 0.f);
    row_gather4(pa0, pa1, xA, lane, eh, el, d);
    if (EMB) row_gather4_emb(pb0, pb1, demb, semb, lane, eh, el, r);
    else     row_gather4(pb0, pb1, xB, lane, eh, el, r);

    // merge halves (identical layout, different edge subsets)
    d.x += __shfl_xor_sync(0xffffffffu, d.x, 16);
    d.y += __shfl_xor_sync(0xffffffffu, d.y, 16);
    d.z += __shfl_xor_sync(0xffffffffu, d.z, 16);
    d.w += __shfl_xor_sync(0xffffffffu, d.w, 16);
    r.x += __shfl_xor_sync(0xffffffffu, r.x, 16);
    r.y += __shfl_xor_sync(0xffffffffu, r.y, 16);
    r.z += __shfl_xor_sync(0xffffffffu, r.z, 16);
    r.w += __shfl_xor_sync(0xffffffffu, r.w, 16);

    // partitionable threefry noise: bits[m] = o0^o1 of threefry(key, 0, m)
    // computed in R11 layout (feats lane*2, lane*2+1), then redistributed via shfl
    unsigned m0 = (unsigned)gw * 64u + (unsigned)(lane * 2);
    uint32_t a0, b0, a1, b1;
    threefry2x32(fk0, fk1, 0u, m0,      a0, b0);
    threefry2x32(fk0, fk1, 0u, m0 + 1u, a1, b1);
    float u0 = u01(a0 ^ b0);
    float u1 = u01(a1 ^ b1);

    float nn = u0 * u0 + u1 * u1;
#pragma unroll
    for (int o = 16; o; o >>= 1) nn += __shfl_xor_sync(0xffffffffu, nn, o);
    float sc = EPSV / fmaxf(sqrtf(nn), 1e-12f);

    // redistribute noise to float4 layout: feat el*4+k lives at lane (el*4+k)>>1
    float n0 = __shfl_sync(0xffffffffu, u0, 2 * el);
    float n1 = __shfl_sync(0xffffffffu, u1, 2 * el);
    float n2 = __shfl_sync(0xffffffffu, u0, 2 * el + 1);
    float n3 = __shfl_sync(0xffffffffu, u1, 2 * el + 1);

    r.x += sgnf(r.x) * n0 * sc;
    r.y += sgnf(r.y) * n1 * sc;
    r.z += sgnf(r.z) * n2 * sc;
    r.w += sgnf(r.w) * n3 * sc;

    // norms: halves hold identical values -> warp reduction = exactly 2x true sum
    float nr = r.x * r.x + r.y * r.y + r.z * r.z + r.w * r.w;
    float np = d.x * d.x + d.y * d.y + d.z * d.z + d.w * d.w;
#pragma unroll
    for (int o = 16; o; o >>= 1) {
        nr += __shfl_xor_sync(0xffffffffu, nr, o);
        np += __shfl_xor_sync(0xffffffffu, np, o);
    }
    nr *= 0.5f;
    np *= 0.5f;
    float ir = 1.0f / fmaxf(sqrtf(nr), 1e-12f);
    float ip = 1.0f / fmaxf(sqrtf(np), 1e-12f);

    if (eh == 0) {
        // rd_stack[:, iter+1, :] = l2n(noised r0)  (scalar stores: odd base offset)
        size_t so = OFF_STACK + (size_t)gw * 256 + (size_t)(iter + 1) * 64 + el * 4;
        out[so]     = r.x * ir;
        out[so + 1] = r.y * ir;
        out[so + 2] = r.z * ir;
        out[so + 3] = r.w * ir;
    }

    float4* sum4 = reinterpret_cast<float4*>(g_sum) + (size_t)gw * 16 + el;
    float4 s = *sum4;

    if (iter < 2) {
        if (eh == 0) {
            s.x += d.x * ip; s.y += d.y * ip; s.z += d.z * ip; s.w += d.w * ip;
            *sum4 = s;
            xOut[(size_t)gw * 16 + el] =
                make_float4(0.5f * (d.x + r.x), 0.5f * (d.y + r.y),
                            0.5f * (d.z + r.z), 0.5f * (d.w + r.w));
        }
    } else if (eh == 0) {
        // fused final: v = mean of 4 layer terms; All = 0.5*rawEmb + 0.5*v
        float4 v4 = make_float4((s.x + d.x * ip) * 0.25f, (s.y + d.y * ip) * 0.25f,
                                (s.z + d.z * ip) * 0.25f, (s.w + d.w * ip) * 0.25f);
        float4 e4 = (gw < DRUGN) ? __ldg(demb + (size_t)gw * 16 + el)
                                 : __ldg(semb + (size_t)(gw - DRUGN) * 16 + el);
        size_t vi = (size_t)gw * 16 + el;
        reinterpret_cast<float4*>(out + OFF_E)[vi] = v4;
        reinterpret_cast<float4*>(out + OFF_ALL)[vi] =
            make_float4(0.5f * e4.x + 0.5f * v4.x, 0.5f * e4.y + 0.5f * v4.y,
                        0.5f * e4.z + 0.5f * v4.z, 0.5f * e4.w + 0.5f * v4.w);
    }
}

// ---------------- host orchestration (graph-capturable) ----------------
extern "C" void kernel_launch(void* const* d_in, const int* in_sizes, int n_in,
                              void* d_out, int out_size)
{
    const float* drug_emb = (const float*)d_in[0];
    const float* dis_emb  = (const float*)d_in[1];
    const float* Wr = (const float*)d_in[2];
    const float* br = (const float*)d_in[3];
    const float* Wd = (const float*)d_in[4];
    const float* bd = (const float*)d_in[5];
    const int*   rr_row = (const int*)d_in[6];
    const int*   rr_col = (const int*)d_in[7];
    const int*   dd_row = (const int*)d_in[9];
    const int*   dd_col = (const int*)d_in[10];
    const int*   rd_row = (const int*)d_in[12];
    const int*   rd_col = (const int*)d_in[13];
    float* out = (float*)d_out;

    void *deg; float *cur0, *curA, *curB;
    cudaGetSymbolAddress(&deg,  g_deg);
    cudaGetSymbolAddress((void**)&cur0, g_cur0);
    cudaGetSymbolAddress((void**)&curA, g_curA);
    cudaGetSymbolAddress((void**)&curB, g_curB);

    // launch 0: fused gate + init (independent of CSR chain)
    gateinit_kernel<<<2048, 256>>>(drug_emb, dis_emb, Wr, br, Wd, bd, out);
    // launch 1: zero degree counts
    cudaMemsetAsync(deg, 0, DEGN * 4);
    // launch 2: degree counts (val == 1)
    degcnt_all<<<(ETOT + 255) / 256, 256>>>(rr_row, rr_col, dd_row, dd_col, rd_row, rd_col);
    // launches 3-4: scan
    scan1_kernel<<<NBLK, 1024>>>();
    scan2_kernel<<<1, 512>>>();
    // launch 5: fill with inline vn
    fill_all<<<(ETOT + 255) / 256, 256>>>(rr_row, rr_col, dd_row, dd_col, rd_row, rd_col);

    // fold_in keys: threefry(key=[0,1], count=[0,i])
    unsigned fk0[3], fk1[3];
    for (int i = 0; i < 3; i++)
        threefry2x32(0u, 1u, 0u, (unsigned)i, fk0[i], fk1[i]);

    // launches 6-8: fused iterations (iter0 reads embs directly; iter2 fuses final)
    iter_kernel<1><<<NRD * 32 / 256, 256>>>((const float4*)cur0, nullptr,
                                            (float4*)curA,
                                            (const float4*)drug_emb, (const float4*)dis_emb,
                                            fk0[0], fk1[0], 0, out);
    iter_kernel<0><<<NRD * 32 / 256, 256>>>((const float4*)curA, (const float4*)curA,
                                            (float4*)curB,
                                            (const float4*)drug_emb, (const float4*)dis_emb,
                                            fk0[1], fk1[1], 1, out);
    iter_kernel<0><<<NRD * 32 / 256, 256>>>((const float4*)curB, (const float4*)curB,
                                            (float4*)curA,
                                            (const float4*)drug_emb, (const float4*)dis_emb,
                                            fk0[2], fk1[2], 2, out);
}

// round 14
// speedup vs baseline: 1.7612x; 1.1110x over previous
#include <cuda_runtime.h>
#include <cstdint>
#include <cstddef>

// ---------------- problem constants ----------------
#define DRUGN 100000
#define DISN  100000
#define NRD   200000            // DRUGN + DISN
#define HIDD  64
#define ERR_  1600000
#define EDD_  1600000
#define ERD_  3200000
#define ETOT  (ERR_ + EDD_ + ERD_)
#define NROWS (DRUGN + DISN + NRD)    // 400000 unified rows: rr | dd | rd
#define NBLK  ((NROWS + 1023) / 1024) // 391 scan blocks
#define DEGN  (2*DRUGN + 2*DISN + 2*NRD)  // 800000 degree slots (int counts; val==1)
#define EPSV  0.1f

// ---------------- output layout (floats) ----------------
#define OFF_E      0            // drugE || disE  (contiguous 12.8M)
#define OFF_ALL    12800000     // drugAll || disAll
#define OFF_RDEMB  25600000     // rd_drug || rd_dis  (= raw embeddings)
#define OFF_LOSS   38400000
#define OFF_STACK  38400001ull  // rd_stack (200000, 4, 64)

// ---------------- scratch (device globals) ----------------
__device__ int   g_deg  [DEGN];          // degree counts (val == 1)
__device__ int   g_lptr [NROWS + 1];     // block-local exclusive prefixes
__device__ int   g_cursor[NROWS];        // fill cursors (block-local)
__device__ int   g_bsum [NBLK];          // exclusive block offsets
__device__ int2  g_epair[ETOT];          // (col, float-bits of vn), unified CSR order
__device__ float g_cur0 [NRD*HIDD];      // gated embeddings rr0 || dd0
__device__ float g_curA [NRD*HIDD];      // ping-pong state buffers
__device__ float g_curB [NRD*HIDD];
__device__ float g_sum  [NRD*HIDD];      // running sum for the layer mean

// ---------------- JAX-exact threefry2x32 (20 rounds) ----------------
__host__ __device__ __forceinline__ void threefry2x32(
    uint32_t k0, uint32_t k1, uint32_t x0, uint32_t x1,
    uint32_t& o0, uint32_t& o1)
{
    uint32_t ks2 = k0 ^ k1 ^ 0x1BD11BDAu;
#define TFR(r) { x0 += x1; x1 = (x1 << (r)) | (x1 >> (32 - (r))); x1 ^= x0; }
    x0 += k0; x1 += k1;
    TFR(13) TFR(15) TFR(26) TFR(6)
    x0 += k1;  x1 += ks2 + 1u;
    TFR(17) TFR(29) TFR(16) TFR(24)
    x0 += ks2; x1 += k0 + 2u;
    TFR(13) TFR(15) TFR(26) TFR(6)
    x0 += k0;  x1 += k1 + 3u;
    TFR(17) TFR(29) TFR(16) TFR(24)
    x0 += k1;  x1 += ks2 + 4u;
    TFR(13) TFR(15) TFR(26) TFR(6)
    x0 += ks2; x1 += k0 + 5u;
#undef TFR
    o0 = x0; o1 = x1;
}

__device__ __forceinline__ float u01(uint32_t b) {
    return __uint_as_float((b >> 9) | 0x3F800000u) - 1.0f;
}
__device__ __forceinline__ float sgnf(float x) {
    return (x > 0.0f) ? 1.0f : ((x < 0.0f) ? -1.0f : 0.0f);
}

// ---------------- fused gate + init (one pass over both embeddings) ----------------
__global__ void gateinit_kernel(const float* __restrict__ de, const float* __restrict__ se,
                                const float* __restrict__ Wr, const float* __restrict__ br,
                                const float* __restrict__ Wd, const float* __restrict__ bd,
                                float* __restrict__ out)
{
    __shared__ float sW[HIDD * HIDD];
    __shared__ float sb[HIDD];
    __shared__ float sE[4][HIDD];
    int t = threadIdx.x;                    // 256 threads
    int half = (blockIdx.x >= 1024);
    const float* emb = half ? se : de;
    const float* W   = half ? Wd : Wr;
    const float* b   = half ? bd : br;
    int nodeBase = half ? DRUGN : 0;
    for (int i = t; i < HIDD * HIDD; i += 256) sW[i] = W[i];
    if (t < HIDD) sb[t] = b[t];
    int j  = t & 63;
    int rs = t >> 6;
    int bl = blockIdx.x & 1023;
    for (int base = bl * 4; base < DRUGN; base += 1024 * 4) {
        int rown = base + rs;
        __syncthreads();
        float ev = emb[rown * HIDD + j];
        sE[rs][j] = ev;
        __syncthreads();
        float acc = sb[j];
#pragma unroll
        for (int k = 0; k < HIDD; k++) acc = fmaf(sE[rs][k], sW[k * HIDD + j], acc);
        float gt = 1.0f / (1.0f + expf(-acc));
        float gv = ev * gt;
        size_t uidx = (size_t)(nodeBase + rown) * HIDD + j;
        g_cur0[uidx] = gv;                  // layer-0 prop input (rr0 || dd0)
        g_sum [uidx] = gv;                  // all_*[0] entry (unnormalized)
        out[OFF_RDEMB + uidx] = ev;         // rd_drug || rd_dis (= raw embeddings)
        out[OFF_STACK + (size_t)(nodeBase + rown) * 256 + j] = ev;  // stack layer 0
    }
    if (blockIdx.x == 0 && t == 0) out[OFF_LOSS] = 0.0f;
}

// ---------------- degree counts over ALL 3 edge lists (val == 1) ----------------
__global__ void degcnt_all(const int* __restrict__ rr_r, const int* __restrict__ rr_c,
                           const int* __restrict__ dd_r, const int* __restrict__ dd_c,
                           const int* __restrict__ rd_r, const int* __restrict__ rd_c)
{
    int e = blockIdx.x * blockDim.x + threadIdx.x;
    if (e >= ETOT) return;
    int r, c; int *dr, *dc;
    if (e < ERR_) {
        r = rr_r[e]; c = rr_c[e];
        dr = g_deg;              dc = g_deg + DRUGN;
    } else if (e < ERR_ + EDD_) {
        int k = e - ERR_;
        r = dd_r[k]; c = dd_c[k];
        dr = g_deg + 2*DRUGN;    dc = g_deg + 2*DRUGN + DISN;
    } else {
        int k = e - ERR_ - EDD_;
        r = rd_r[k]; c = rd_c[k];
        dr = g_deg + 2*DRUGN + 2*DISN; dc = dr + NRD;
    }
    atomicAdd(dr + r, 1);
    atomicAdd(dc + c, 1);
}

// row count for unified row i lives in the corresponding dr slot
__device__ __forceinline__ int row_count(int i)
{
    if (i < DRUGN)       return g_deg[i];                         // dr_rr
    if (i < 2*DRUGN)     return g_deg[2*DRUGN + (i - DRUGN)];     // dr_dd
    return g_deg[2*DRUGN + 2*DISN + (i - NRD)];                   // dr_rd
}

// ---------------- scan1: block-local exclusive prefix + cursor + block totals -------
__global__ void scan1_kernel()
{
    __shared__ int sw[32];
    int b = blockIdx.x, t = threadIdx.x;
    int lane = t & 31, wid = t >> 5;
    int i = b * 1024 + t;
    int v = (i < NROWS) ? row_count(i) : 0;
    int inc = v;
#pragma unroll
    for (int o = 1; o < 32; o <<= 1) {
        int u = __shfl_up_sync(0xffffffffu, inc, o);
        if (lane >= o) inc += u;
    }
    if (lane == 31) sw[wid] = inc;
    __syncthreads();
    if (wid == 0) {
        int s = sw[lane];
#pragma unroll
        for (int o = 1; o < 32; o <<= 1) {
            int u = __shfl_up_sync(0xffffffffu, s, o);
            if (lane >= o) s += u;
        }
        sw[lane] = s;
    }
    __syncthreads();
    int woff = wid ? sw[wid - 1] : 0;
    int excl = woff + inc - v;
    if (i <= NROWS) g_lptr[i] = excl;       // includes sentinel slot i == NROWS
    if (i <  NROWS) g_cursor[i] = excl;
    if (t == 0)     g_bsum[b] = sw[31];
}

// ---------------- scan2: exclusive scan of 391 block totals (1 block) ----------------
__global__ void scan2_kernel()
{
    __shared__ int sw[16];
    int t = threadIdx.x;           // 512 threads
    int lane = t & 31, wid = t >> 5;
    int v = (t < NBLK) ? g_bsum[t] : 0;
    int inc = v;
#pragma unroll
    for (int o = 1; o < 32; o <<= 1) {
        int u = __shfl_up_sync(0xffffffffu, inc, o);
        if (lane >= o) inc += u;
    }
    if (lane == 31) sw[wid] = inc;
    __syncthreads();
    if (wid == 0 && lane < 16) {
        int s = sw[lane];
#pragma unroll
        for (int o = 1; o < 16; o <<= 1) {
            int u = __shfl_up_sync(0x0000ffffu, s, o);
            if (lane >= o) s += u;
        }
        sw[lane] = s;
    }
    __syncthreads();
    int excl = (wid ? sw[wid - 1] : 0) + inc - v;
    if (t < NBLK) g_bsum[t] = excl;
}

// ---------------- fill: vn inline (val==1), absolute pos = cursor + bsum ------------
__global__ void fill_all(const int* __restrict__ rr_r, const int* __restrict__ rr_c,
                         const int* __restrict__ dd_r, const int* __restrict__ dd_c,
                         const int* __restrict__ rd_r, const int* __restrict__ rd_c)
{
    int e = blockIdx.x * blockDim.x + threadIdx.x;
    if (e >= ETOT) return;
    int r, c; const int *dr, *dc; int rowOff, colOff;
    if (e < ERR_) {
        r = rr_r[e]; c = rr_c[e];
        dr = g_deg;                    dc = g_deg + DRUGN;
        rowOff = 0;                    colOff = 0;
    } else if (e < ERR_ + EDD_) {
        int k = e - ERR_;
        r = dd_r[k]; c = dd_c[k];
        dr = g_deg + 2*DRUGN;          dc = g_deg + 2*DRUGN + DISN;
        rowOff = DRUGN;                colOff = DRUGN;
    } else {
        int k = e - ERR_ - EDD_;
        r = rd_r[k]; c = rd_c[k];
        dr = g_deg + 2*DRUGN + 2*DISN; dc = dr + NRD;
        rowOff = NRD;                  colOff = 0;
    }
    float vn = rsqrtf(fmaxf((float)dr[r] * (float)dc[c], 1e-12f));
    int urow = r + rowOff;
    int p = atomicAdd(g_cursor + urow, 1) + g_bsum[urow >> 10];
    g_epair[p] = make_int2(c + colOff, __float_as_int(vn));
}

// ---------------- warp row gather: coalesced edge load + shfl broadcast -------------
// R11-proven structure: unpredicated body, uniform loop bound, one float2 per lane.
__device__ __forceinline__ void row_gather(int p0, int p1, const float2* __restrict__ x,
                                           int lane, float& ax, float& ay)
{
    for (int base = p0; base < p1; base += 32) {
        int idx = base + lane;
        int2 ee = (idx < p1) ? __ldg(g_epair + idx) : make_int2(0, 0);
        int m = min(32, p1 - base);
#pragma unroll 8
        for (int jj = 0; jj < m; jj++) {
            int   c = __shfl_sync(0xffffffffu, ee.x, jj);
            float v = __int_as_float(__shfl_sync(0xffffffffu, ee.y, jj));
            float2 xv = __ldg(x + (size_t)c * 32 + lane);
            ax = fmaf(v, xv.x, ax);
            ay = fmaf(v, xv.y, ay);
        }
    }
}

// iter-0 rd gather: columns index concat(drug_emb, dis_emb) — per-col pointer select
__device__ __forceinline__ void row_gather_emb(int p0, int p1,
                                               const float2* __restrict__ de,
                                               const float2* __restrict__ se,
                                               int lane, float& ax, float& ay)
{
    for (int base = p0; base < p1; base += 32) {
        int idx = base + lane;
        int2 ee = (idx < p1) ? __ldg(g_epair + idx) : make_int2(0, 0);
        int m = min(32, p1 - base);
#pragma unroll 8
        for (int jj = 0; jj < m; jj++) {
            int   c = __shfl_sync(0xffffffffu, ee.x, jj);
            float v = __int_as_float(__shfl_sync(0xffffffffu, ee.y, jj));
            const float2* xb = (c < DRUGN) ? (de + (size_t)c * 32)
                                           : (se + (size_t)(c - DRUGN) * 32);
            float2 xv = __ldg(xb + lane);
            ax = fmaf(v, xv.x, ax);
            ay = fmaf(v, xv.y, ay);
        }
    }
}

// ---------------- fused iteration: spmm both rows + noise + norms + update ----------
// iter==2 additionally emits drugE/disE/drugAll/disAll (final_kernel fused in).
template<int EMB>
__global__ void iter_kernel(const float2* __restrict__ xA, const float2* __restrict__ xB,
                            float2* __restrict__ xOut,
                            const float2* __restrict__ demb, const float2* __restrict__ semb,
                            unsigned fk0, unsigned fk1, int iter, float* __restrict__ out)
{
    int gw   = (blockIdx.x * blockDim.x + threadIdx.x) >> 5;   // node 0..NRD-1
    int lane = threadIdx.x & 31;
    if (gw >= NRD) return;

    int pa0 = g_lptr[gw]           + g_bsum[gw >> 10];
    int pa1 = g_lptr[gw + 1]       + g_bsum[(gw + 1) >> 10];
    int pb0 = g_lptr[gw + NRD]     + g_bsum[(gw + NRD) >> 10];
    int pb1 = g_lptr[gw + NRD + 1] + g_bsum[(gw + NRD + 1) >> 10];

    float dx = 0.0f, dy = 0.0f, rx = 0.0f, ry = 0.0f;
    row_gather(pa0, pa1, xA, lane, dx, dy);
    if (EMB) row_gather_emb(pb0, pb1, demb, semb, lane, rx, ry);
    else     row_gather(pb0, pb1, xB, lane, rx, ry);

    // partitionable threefry noise: bits[m] = o0^o1 of threefry(key, 0, m)
    unsigned m0 = (unsigned)gw * 64u + (unsigned)(lane * 2);
    uint32_t a0, b0, a1, b1;
    threefry2x32(fk0, fk1, 0u, m0,      a0, b0);
    threefry2x32(fk0, fk1, 0u, m0 + 1u, a1, b1);
    float u0 = u01(a0 ^ b0);
    float u1 = u01(a1 ^ b1);

    float nn = u0 * u0 + u1 * u1;
#pragma unroll
    for (int o = 16; o; o >>= 1) nn += __shfl_xor_sync(0xffffffffu, nn, o);
    float sc = EPSV / fmaxf(sqrtf(nn), 1e-12f);

    rx += sgnf(rx) * u0 * sc;
    ry += sgnf(ry) * u1 * sc;

    float nr = rx * rx + ry * ry;
    float np = dx * dx + dy * dy;
#pragma unroll
    for (int o = 16; o; o >>= 1) {
        nr += __shfl_xor_sync(0xffffffffu, nr, o);
        np += __shfl_xor_sync(0xffffffffu, np, o);
    }
    float ir = 1.0f / fmaxf(sqrtf(nr), 1e-12f);
    float ip = 1.0f / fmaxf(sqrtf(np), 1e-12f);

    // rd_stack[:, iter+1, :] = l2n(noised r0)
    size_t so = OFF_STACK + (size_t)gw * 256 + (size_t)(iter + 1) * 64 + lane * 2;
    out[so]     = rx * ir;
    out[so + 1] = ry * ir;

    float2* sum2 = reinterpret_cast<float2*>(g_sum) + (size_t)gw * 32 + lane;
    float2 s = *sum2;

    if (iter < 2) {
        s.x += dx * ip;
        s.y += dy * ip;
        *sum2 = s;
        xOut[(size_t)gw * 32 + lane] = make_float2(0.5f * (dx + rx), 0.5f * (dy + ry));
    } else {
        // fused final: v = mean of 4 layer terms; All = 0.5*rawEmb + 0.5*v
        float vx = (s.x + dx * ip) * 0.25f;
        float vy = (s.y + dy * ip) * 0.25f;
        float2 e = (gw < DRUGN) ? __ldg(demb + (size_t)gw * 32 + lane)
                                : __ldg(semb + (size_t)(gw - DRUGN) * 32 + lane);
        size_t uidx = (size_t)gw * 64 + lane * 2;
        out[OFF_E   + uidx]     = vx;
        out[OFF_E   + uidx + 1] = vy;
        out[OFF_ALL + uidx]     = 0.5f * e.x + 0.5f * vx;
        out[OFF_ALL + uidx + 1] = 0.5f * e.y + 0.5f * vy;
    }
}

// ---------------- host orchestration (graph-capturable) ----------------
extern "C" void kernel_launch(void* const* d_in, const int* in_sizes, int n_in,
                              void* d_out, int out_size)
{
    const float* drug_emb = (const float*)d_in[0];
    const float* dis_emb  = (const float*)d_in[1];
    const float* Wr = (const float*)d_in[2];
    const float* br = (const float*)d_in[3];
    const float* Wd = (const float*)d_in[4];
    const float* bd = (const float*)d_in[5];
    const int*   rr_row = (const int*)d_in[6];
    const int*   rr_col = (const int*)d_in[7];
    const int*   dd_row = (const int*)d_in[9];
    const int*   dd_col = (const int*)d_in[10];
    const int*   rd_row = (const int*)d_in[12];
    const int*   rd_col = (const int*)d_in[13];
    float* out = (float*)d_out;

    void *deg; float *cur0, *curA, *curB;
    cudaGetSymbolAddress(&deg,  g_deg);
    cudaGetSymbolAddress((void**)&cur0, g_cur0);
    cudaGetSymbolAddress((void**)&curA, g_curA);
    cudaGetSymbolAddress((void**)&curB, g_curB);

    // launch 0: fused gate + init (independent of CSR chain)
    gateinit_kernel<<<2048, 256>>>(drug_emb, dis_emb, Wr, br, Wd, bd, out);
    // launch 1: zero degree counts
    cudaMemsetAsync(deg, 0, DEGN * 4);
    // launch 2: degree counts (val == 1)
    degcnt_all<<<(ETOT + 255) / 256, 256>>>(rr_row, rr_col, dd_row, dd_col, rd_row, rd_col);
    // launches 3-4: scan
    scan1_kernel<<<NBLK, 1024>>>();
    scan2_kernel<<<1, 512>>>();
    // launch 5: fill with inline vn
    fill_all<<<(ETOT + 255) / 256, 256>>>(rr_row, rr_col, dd_row, dd_col, rd_row, rd_col);

    // fold_in keys: threefry(key=[0,1], count=[0,i])
    unsigned fk0[3], fk1[3];
    for (int i = 0; i < 3; i++)
        threefry2x32(0u, 1u, 0u, (unsigned)i, fk0[i], fk1[i]);

    // launches 6-8: fused iterations (iter0 reads embs directly; iter2 fuses final)
    iter_kernel<1><<<NRD * 32 / 256, 256>>>((const float2*)cur0, nullptr,
                                            (float2*)curA,
                                            (const float2*)drug_emb, (const float2*)dis_emb,
                                            fk0[0], fk1[0], 0, out);
    iter_kernel<0><<<NRD * 32 / 256, 256>>>((const float2*)curA, (const float2*)curA,
                                            (float2*)curB,
                                            (const float2*)drug_emb, (const float2*)dis_emb,
                                            fk0[1], fk1[1], 1, out);
    iter_kernel<0><<<NRD * 32 / 256, 256>>>((const float2*)curB, (const float2*)curB,
                                            (float2*)curA,
                                            (const float2*)drug_emb, (const float2*)dis_emb,
                                            fk0[2], fk1[2], 2, out);
}